// round 5
// baseline (speedup 1.0000x reference)
#include <cuda_runtime.h>
#include <math.h>

// ---------------- problem constants ----------------
#define NNODES 50000
#define NEDGES 600000
#define DIM    128
#define NET    4
#define NSTEPS 5
#define NGR    64

// ---------------- scratch (device globals; no allocation allowed) ----------------
__device__ float g_t[NET * NNODES * DIM];        // 102.4 MB per-etype transformed feats
__device__ float g_h[NNODES * DIM];              // hidden state
__device__ float g_a[NNODES * DIM];              // aggregated messages
__device__ float g_gi[NNODES * 3 * DIM];         // GRU input gates
__device__ float g_gh[NNODES * 3 * DIM];         // GRU hidden gates
__device__ float g_z[NNODES * 2 * DIM];          // zft [N,2,128]
__device__ float g_gat[NNODES * 2 * DIM];        // GAT output
__device__ float g_el[NNODES * 2];
__device__ float g_er[NNODES * 2];
__device__ int   g_deg[NNODES];
__device__ int   g_off[NNODES + 1];
__device__ int   g_cur[NNODES + 1];
__device__ int   g_cgidx[NEDGES];                // etype*N + src, dst-sorted
__device__ int   g_csrc[NEDGES];                 // src, dst-sorted
__device__ float g_hg[NGR * 2 * DIM];
__device__ float g_cls[2 * NGR * 2 * 32];

// ---------------- tiled fp32 GEMM: C[m,c] = sum_k A[m,k]*B[c,k] + bias[c] ----------------
// A: [M,128] row-major, B: [Ncols,128] row-major, K fixed = 128.
// blockIdx.z batches B/C/bias (for the 4 etype weights).
__global__ __launch_bounds__(256) void sgemm_tn(
    const float* __restrict__ A, const float* __restrict__ B,
    const float* __restrict__ bias, float* __restrict__ C,
    int M, int Ncols, int strideB, int strideC, int strideBias)
{
    __shared__ __align__(16) float As[16][128];
    __shared__ __align__(16) float Bs[16][128];

    const int bz = blockIdx.z;
    B += (size_t)bz * strideB;
    C += (size_t)bz * strideC;
    const float* bptr = bias ? (bias + (size_t)bz * strideBias) : nullptr;

    const int rowBase = blockIdx.y * 128;
    const int colBase = blockIdx.x * 128;
    const int tid  = threadIdx.x;
    const int tRow = (tid >> 4) * 8;
    const int tCol = (tid & 15) * 8;

    float acc[8][8];
#pragma unroll
    for (int i = 0; i < 8; i++)
#pragma unroll
        for (int j = 0; j < 8; j++) acc[i][j] = 0.f;

    for (int kk = 0; kk < DIM; kk += 16) {
#pragma unroll
        for (int i = 0; i < 2; i++) {
            int idx = tid + i * 256;          // 0..511
            int row = idx >> 2;               // 0..127
            int k4  = (idx & 3) * 4;          // 0,4,8,12
            int gr = rowBase + row;
            float4 va = make_float4(0.f, 0.f, 0.f, 0.f);
            if (gr < M) va = *reinterpret_cast<const float4*>(A + (size_t)gr * DIM + kk + k4);
            As[k4 + 0][row] = va.x; As[k4 + 1][row] = va.y;
            As[k4 + 2][row] = va.z; As[k4 + 3][row] = va.w;
            int gc = colBase + row;
            float4 vb = make_float4(0.f, 0.f, 0.f, 0.f);
            if (gc < Ncols) vb = *reinterpret_cast<const float4*>(B + (size_t)gc * DIM + kk + k4);
            Bs[k4 + 0][row] = vb.x; Bs[k4 + 1][row] = vb.y;
            Bs[k4 + 2][row] = vb.z; Bs[k4 + 3][row] = vb.w;
        }
        __syncthreads();
#pragma unroll
        for (int k = 0; k < 16; k++) {
            float4 a0 = *reinterpret_cast<const float4*>(&As[k][tRow]);
            float4 a1 = *reinterpret_cast<const float4*>(&As[k][tRow + 4]);
            float4 b0 = *reinterpret_cast<const float4*>(&Bs[k][tCol]);
            float4 b1 = *reinterpret_cast<const float4*>(&Bs[k][tCol + 4]);
            float ra[8] = {a0.x, a0.y, a0.z, a0.w, a1.x, a1.y, a1.z, a1.w};
            float rb[8] = {b0.x, b0.y, b0.z, b0.w, b1.x, b1.y, b1.z, b1.w};
#pragma unroll
            for (int i = 0; i < 8; i++)
#pragma unroll
                for (int j = 0; j < 8; j++)
                    acc[i][j] = fmaf(ra[i], rb[j], acc[i][j]);
        }
        __syncthreads();
    }

#pragma unroll
    for (int i = 0; i < 8; i++) {
        int r = rowBase + tRow + i;
        if (r >= M) continue;
#pragma unroll
        for (int j = 0; j < 8; j++) {
            int c = colBase + tCol + j;
            if (c < Ncols) {
                float v = acc[i][j];
                if (bptr) v += bptr[c];
                C[(size_t)r * Ncols + c] = v;
            }
        }
    }
}

// ---------------- CSR construction ----------------
__global__ void zero_int_kernel(int* p, int n) {
    int i = blockIdx.x * blockDim.x + threadIdx.x;
    if (i < n) p[i] = 0;
}

__global__ void hist_kernel(const int* __restrict__ dst, int* deg, int E) {
    int i = blockIdx.x * blockDim.x + threadIdx.x;
    if (i < E) atomicAdd(&deg[dst[i]], 1);
}

__global__ void scan_kernel(const int* __restrict__ deg, int* off, int* cur, int n) {
    __shared__ int tmp[1024];
    __shared__ int carry_s;
    int t = threadIdx.x;
    if (t == 0) { off[0] = 0; cur[0] = 0; carry_s = 0; }
    __syncthreads();
    for (int base = 0; base < n; base += 1024) {
        int v = (base + t < n) ? deg[base + t] : 0;
        tmp[t] = v;
        __syncthreads();
        for (int s = 1; s < 1024; s <<= 1) {
            int x = (t >= s) ? tmp[t - s] : 0;
            __syncthreads();
            tmp[t] += x;
            __syncthreads();
        }
        int incl = tmp[t] + carry_s;
        if (base + t < n) { off[base + t + 1] = incl; cur[base + t + 1] = incl; }
        __syncthreads();
        if (t == 1023) carry_s = incl;
        __syncthreads();
    }
}

__global__ void scatter_kernel(const int* __restrict__ src, const int* __restrict__ dst,
                               const int* __restrict__ et, int* cur,
                               int* cgidx, int* csrc, int E, int n) {
    int i = blockIdx.x * blockDim.x + threadIdx.x;
    if (i >= E) return;
    int d = dst[i];
    int p = atomicAdd(&cur[d], 1);
    int s = src[i];
    cgidx[p] = et[i] * n + s;
    csrc[p]  = s;
}

// ---------------- GGC: message aggregation (segment_sum over dst) ----------------
__global__ void agg_kernel(const int* __restrict__ off, const int* __restrict__ cgidx,
                           const float* __restrict__ t, float* __restrict__ a) {
    int n = blockIdx.x, tid = threadIdx.x;  // 128 threads = features
    int s = off[n], e = off[n + 1];
    float acc = 0.f;
    for (int i = s; i < e; i++) {
        int g = __ldg(&cgidx[i]);
        acc += __ldg(&t[(size_t)g * DIM + tid]);
    }
    a[(size_t)n * DIM + tid] = acc;
}

// ---------------- GRU elementwise ----------------
__global__ void gru_kernel(const float* __restrict__ gi, const float* __restrict__ gh,
                           const float* __restrict__ hold, float* __restrict__ hnew, int n) {
    int idx = blockIdx.x * blockDim.x + threadIdx.x;
    if (idx >= n * DIM) return;
    int node = idx >> 7, d = idx & 127;
    const float* gip = gi + (size_t)node * 384;
    const float* ghp = gh + (size_t)node * 384;
    float r  = 1.f / (1.f + expf(-(gip[d] + ghp[d])));
    float zq = 1.f / (1.f + expf(-(gip[128 + d] + ghp[128 + d])));
    float nn = tanhf(gip[256 + d] + r * ghp[256 + d]);
    float h0 = hold[idx];
    hnew[idx] = (1.f - zq) * nn + zq * h0;
}

// ---------------- L2 normalize + sigmoid ----------------
__global__ void normsig_kernel(float* __restrict__ h) {
    int n = blockIdx.x, tid = threadIdx.x;  // 128
    __shared__ float red[128];
    float v = h[(size_t)n * DIM + tid];
    red[tid] = v * v;
    __syncthreads();
    for (int s = 64; s; s >>= 1) {
        if (tid < s) red[tid] += red[tid + s];
        __syncthreads();
    }
    float norm = fmaxf(sqrtf(red[0]), 1e-12f);
    float x = v / norm;
    h[(size_t)n * DIM + tid] = 1.f / (1.f + expf(-x));
}

// ---------------- GAT: el/er per node ----------------
__global__ void eler_kernel(const float* __restrict__ z, const float* __restrict__ al,
                            const float* __restrict__ ar, float* __restrict__ el,
                            float* __restrict__ er) {
    int n = blockIdx.x, tid = threadIdx.x;  // 256 = (head, d)
    __shared__ float sl[256], sr[256];
    float zv = z[(size_t)n * 256 + tid];
    sl[tid] = zv * al[tid];
    sr[tid] = zv * ar[tid];
    __syncthreads();
    int lane = tid & 127;
    for (int s = 64; s; s >>= 1) {
        if (lane < s) { sl[tid] += sl[tid + s]; sr[tid] += sr[tid + s]; }
        __syncthreads();
    }
    if (lane == 0) {
        int h = tid >> 7;
        el[n * 2 + h] = sl[tid];
        er[n * 2 + h] = sr[tid];
    }
}

// ---------------- GAT: edge softmax + weighted aggregation per dst node ----------------
__global__ void gat_kernel(const int* __restrict__ off, const int* __restrict__ csrc,
                           const float* __restrict__ el, const float* __restrict__ er,
                           const float* __restrict__ z, const float* __restrict__ bias,
                           float* __restrict__ outp) {
    int n = blockIdx.x, tid = threadIdx.x;  // 256 = (head, d)
    int h = tid >> 7, lane = tid & 127;
    int s0 = off[n], s1 = off[n + 1];
    float er_nh = er[n * 2 + h];

    __shared__ float red[256];
    __shared__ float mden[4];       // m[2], invden[2]
    __shared__ float wbuf[2][128];
    __shared__ int   sbuf[128];

    // pass 1: per-head max of leaky_relu(el[src]+er[n])
    float lmax = -3.0e38f;
    for (int e = s0 + lane; e < s1; e += 128) {
        float x = el[csrc[e] * 2 + h] + er_nh;
        x = x > 0.f ? x : 0.2f * x;
        lmax = fmaxf(lmax, x);
    }
    red[tid] = lmax;
    __syncthreads();
    for (int s = 64; s; s >>= 1) {
        if (lane < s) red[tid] = fmaxf(red[tid], red[tid + s]);
        __syncthreads();
    }
    if (lane == 0) mden[h] = red[tid];
    __syncthreads();
    float m = mden[h];

    // pass 2: denominator
    float lsum = 0.f;
    for (int e = s0 + lane; e < s1; e += 128) {
        float x = el[csrc[e] * 2 + h] + er_nh;
        x = x > 0.f ? x : 0.2f * x;
        lsum += expf(x - m);
    }
    red[tid] = lsum;
    __syncthreads();
    for (int s = 64; s; s >>= 1) {
        if (lane < s) red[tid] += red[tid + s];
        __syncthreads();
    }
    if (lane == 0) mden[2 + h] = 1.f / red[tid];
    __syncthreads();
    float invden = mden[2 + h];

    // pass 3: chunked weighted accumulation of zft[src]
    float acc = 0.f;
    for (int base = s0; base < s1; base += 128) {
        int cnt = min(128, s1 - base);
        if (lane < cnt) {
            int sn = csrc[base + lane];
            float x = el[sn * 2 + h] + er_nh;
            x = x > 0.f ? x : 0.2f * x;
            wbuf[h][lane] = expf(x - m) * invden;
            if (h == 0) sbuf[lane] = sn;
        }
        __syncthreads();
        for (int i = 0; i < cnt; i++)
            acc = fmaf(wbuf[h][i], z[(size_t)sbuf[i] * 256 + tid], acc);
        __syncthreads();
    }
    float o = acc + bias[tid];
    outp[(size_t)n * 256 + tid] = fmaxf(o, 0.f);
}

// ---------------- graph mean-pool (gid sorted -> binary search ranges) ----------------
__global__ void pool_kernel(const int* __restrict__ gid, const float* __restrict__ hgat,
                            float* __restrict__ hg, int n) {
    int b = blockIdx.x, tid = threadIdx.x;  // 256
    __shared__ int s_lo, s_hi;
    if (tid == 0) {
        int lo = 0, hi = n;
        while (lo < hi) { int mid = (lo + hi) >> 1; if (gid[mid] < b) lo = mid + 1; else hi = mid; }
        s_lo = lo;
        lo = 0; hi = n;
        while (lo < hi) { int mid = (lo + hi) >> 1; if (gid[mid] < b + 1) lo = mid + 1; else hi = mid; }
        s_hi = lo;
    }
    __syncthreads();
    float acc = 0.f;
    for (int node = s_lo; node < s_hi; node++)
        acc += hgat[(size_t)node * 256 + tid];
    float cnt = (float)(s_hi - s_lo);
    hg[b * 256 + tid] = acc / fmaxf(cnt, 1.f);
}

// ---------------- classifier ----------------
__global__ void cls_kernel(const float* __restrict__ hg, const float* __restrict__ Wc,
                           const float* __restrict__ bc, float* __restrict__ outc) {
    int b = blockIdx.x, tid = threadIdx.x;  // 64 = (head, c)
    __shared__ float sh[256];
    for (int i = tid; i < 256; i += 64) sh[i] = hg[b * 256 + i];
    __syncthreads();
    int h = tid >> 5, c = tid & 31;
    float s = bc[c];
    for (int d = 0; d < DIM; d++)
        s = fmaf(sh[h * 128 + d], Wc[c * 128 + d], s);
    outc[b * 64 + tid] = s;
}

// ---------------- pairwise distance + softmax over heads ----------------
__global__ void final_kernel(const float* __restrict__ c1, const float* __restrict__ c2,
                             float* __restrict__ out) {
    int b = threadIdx.x;
    if (b >= NGR) return;
    float dist[2];
    for (int h = 0; h < 2; h++) {
        float ss = 0.f;
        for (int c = 0; c < 32; c++) {
            float diff = c1[b * 64 + h * 32 + c] - c2[b * 64 + h * 32 + c] + 1e-6f;
            ss += diff * diff;
        }
        dist[h] = sqrtf(ss);
    }
    float mx = fmaxf(dist[0], dist[1]);
    float e0 = expf(dist[0] - mx), e1 = expf(dist[1] - mx);
    float inv = 1.f / (e0 + e1);
    out[b * 2 + 0] = e0 * inv;
    out[b * 2 + 1] = e1 * inv;
}

// ---------------- host launcher ----------------
extern "C" void kernel_launch(void* const* d_in, const int* in_sizes, int n_in,
                              void* d_out, int out_size) {
    const float* feat[2] = {(const float*)d_in[0], (const float*)d_in[1]};
    const int* srcs[2] = {(const int*)d_in[2], (const int*)d_in[6]};
    const int* dsts[2] = {(const int*)d_in[3], (const int*)d_in[7]};
    const int* ets[2]  = {(const int*)d_in[4], (const int*)d_in[8]};
    const int* gids[2] = {(const int*)d_in[5], (const int*)d_in[9]};
    const float* W_et   = (const float*)d_in[10];
    const float* b_et   = (const float*)d_in[11];
    const float* W_ih   = (const float*)d_in[12];
    const float* W_hh   = (const float*)d_in[13];
    const float* b_ih   = (const float*)d_in[14];
    const float* b_hh   = (const float*)d_in[15];
    const float* W_fc   = (const float*)d_in[16];
    const float* attn_l = (const float*)d_in[17];
    const float* attn_r = (const float*)d_in[18];
    const float* g_bias = (const float*)d_in[19];
    const float* W_cls  = (const float*)d_in[20];
    const float* b_cls  = (const float*)d_in[21];

    int N = in_sizes[0] / DIM;
    int E = in_sizes[2];

    float *t, *h, *a, *gi, *gh, *z, *gat, *el, *er, *hg, *cls;
    int *deg, *off, *cur, *cgidx, *csrc;
    cudaGetSymbolAddress((void**)&t, g_t);
    cudaGetSymbolAddress((void**)&h, g_h);
    cudaGetSymbolAddress((void**)&a, g_a);
    cudaGetSymbolAddress((void**)&gi, g_gi);
    cudaGetSymbolAddress((void**)&gh, g_gh);
    cudaGetSymbolAddress((void**)&z, g_z);
    cudaGetSymbolAddress((void**)&gat, g_gat);
    cudaGetSymbolAddress((void**)&el, g_el);
    cudaGetSymbolAddress((void**)&er, g_er);
    cudaGetSymbolAddress((void**)&deg, g_deg);
    cudaGetSymbolAddress((void**)&off, g_off);
    cudaGetSymbolAddress((void**)&cur, g_cur);
    cudaGetSymbolAddress((void**)&cgidx, g_cgidx);
    cudaGetSymbolAddress((void**)&csrc, g_csrc);
    cudaGetSymbolAddress((void**)&hg, g_hg);
    cudaGetSymbolAddress((void**)&cls, g_cls);

    int mblocks = (N + 127) / 128;

    for (int g = 0; g < 2; g++) {
        // CSR by dst
        zero_int_kernel<<<(N + 255) / 256, 256>>>(deg, N);
        hist_kernel<<<(E + 255) / 256, 256>>>(dsts[g], deg, E);
        scan_kernel<<<1, 1024>>>(deg, off, cur, N);
        scatter_kernel<<<(E + 255) / 256, 256>>>(srcs[g], dsts[g], ets[g], cur, cgidx, csrc, E, N);

        const float* hcur = feat[g];
        for (int s = 0; s < NSTEPS; s++) {
            // t[k] = hcur @ W_et[k]^T + b_et[k]   (batched over k)
            sgemm_tn<<<dim3(1, mblocks, NET), 256>>>(hcur, W_et, b_et, t,
                                                     N, DIM, DIM * DIM, N * DIM, DIM);
            // a = segment_sum(t[etype,src], dst)
            agg_kernel<<<N, DIM>>>(off, cgidx, t, a);
            // GRU gates
            sgemm_tn<<<dim3(3, mblocks, 1), 256>>>(a, W_ih, b_ih, gi, N, 3 * DIM, 0, 0, 0);
            sgemm_tn<<<dim3(3, mblocks, 1), 256>>>(hcur, W_hh, b_hh, gh, N, 3 * DIM, 0, 0, 0);
            gru_kernel<<<(N * DIM + 255) / 256, 256>>>(gi, gh, hcur, h, N);
            hcur = h;
        }

        normsig_kernel<<<N, DIM>>>(h);

        // GAT
        sgemm_tn<<<dim3(2, mblocks, 1), 256>>>(h, W_fc, nullptr, z, N, 2 * DIM, 0, 0, 0);
        eler_kernel<<<N, 256>>>(z, attn_l, attn_r, el, er);
        gat_kernel<<<N, 256>>>(off, csrc, el, er, z, g_bias, gat);

        // pool + classify
        pool_kernel<<<NGR, 256>>>(gids[g], gat, hg, N);
        cls_kernel<<<NGR, 64>>>(hg, W_cls, b_cls, cls + g * NGR * 64);
    }

    final_kernel<<<1, 64>>>(cls, cls + NGR * 64, (float*)d_out);
}

// round 7
// speedup vs baseline: 1.7676x; 1.7676x over previous
#include <cuda_runtime.h>
#include <cuda_bf16.h>
#include <math.h>

// ---------------- problem constants ----------------
#define NNODES 50000
#define NEDGES 600000
#define DIM    128
#define NET    4
#define NSTEPS 5
#define NGR    64

// ---------------- scratch (device globals; no allocation allowed) ----------------
__device__ float g_t[NET * NNODES * DIM];        // per-etype transformed feats
__device__ float g_h[NNODES * DIM];              // hidden state
__device__ float g_a[NNODES * DIM];              // aggregated messages
__device__ float g_gi[NNODES * 3 * DIM];         // GRU input gates
__device__ float g_gh[NNODES * 3 * DIM];         // GRU hidden gates
__device__ float g_z[NNODES * 2 * DIM];          // zft [N,2,128]
__device__ float g_gat[NNODES * 2 * DIM];        // GAT output
__device__ float g_el[NNODES * 2];
__device__ float g_er[NNODES * 2];
__device__ int   g_deg[NNODES];
__device__ int   g_off[NNODES + 1];
__device__ int   g_cur[NNODES + 1];
__device__ int   g_cgidx[NEDGES];                // etype*N + src, dst-sorted
__device__ int   g_csrc[NEDGES];                 // src, dst-sorted
__device__ float g_hg[NGR * 2 * DIM];
__device__ float g_cls[2 * NGR * 2 * 32];

// =====================================================================
// bf16 split tensor-core GEMM:  C[m,c] = sum_k A[m,k]*B[c,k] (+ bias[c])
// A: [M,128] fp32 row-major.  B: [Ncols,128] fp32 row-major.  K = 128.
// fp32 emulated as hi+lo bf16 split, 3 MMA passes, fp32 accumulate.
// Block tile 128x128, 8 warps of 64x32, BK=32.
// blockIdx.z batches over B/C/bias (for the 4 etype weights).
// =====================================================================
#define BKQ 32
#define APAD 8
#define LDA (BKQ + APAD)   // 40 bf16 per row = 80B, conflict-free frag loads

__device__ __forceinline__ void mma16816(float* c, const unsigned* a, const unsigned* b) {
    asm volatile(
        "mma.sync.aligned.m16n8k16.row.col.f32.bf16.bf16.f32 "
        "{%0,%1,%2,%3},{%4,%5,%6,%7},{%8,%9},{%0,%1,%2,%3};"
        : "+f"(c[0]), "+f"(c[1]), "+f"(c[2]), "+f"(c[3])
        : "r"(a[0]), "r"(a[1]), "r"(a[2]), "r"(a[3]), "r"(b[0]), "r"(b[1]));
}

__global__ __launch_bounds__(256) void bgemm_tn(
    const float* __restrict__ A, const float* __restrict__ B,
    const float* __restrict__ bias, float* __restrict__ C,
    int M, int Ncols, int strideB, int strideC, int strideBias)
{
    __shared__ __align__(16) __nv_bfloat16 Ash[2][128][LDA];   // [hi/lo][row][k]
    __shared__ __align__(16) __nv_bfloat16 Bsh[2][128][LDA];

    const int bz = blockIdx.z;
    B += (size_t)bz * strideB;
    C += (size_t)bz * strideC;
    const float* bp = bias ? (bias + (size_t)bz * strideBias) : nullptr;

    const int rowBase = blockIdx.y * 128;
    const int colBase = blockIdx.x * 128;
    const int tid = threadIdx.x;
    const int warp = tid >> 5, lane = tid & 31;
    const int wm = warp >> 2, wn = warp & 3;        // 2 x 4 warp grid
    const int warpRow = wm * 64, warpCol = wn * 32;
    const int rr = lane >> 2;                        // 0..7
    const int cc = (lane & 3) * 2;                   // 0,2,4,6

    float acc[4][4][4];
#pragma unroll
    for (int i = 0; i < 4; i++)
#pragma unroll
        for (int j = 0; j < 4; j++)
#pragma unroll
            for (int q = 0; q < 4; q++) acc[i][j][q] = 0.f;

    for (int kk = 0; kk < DIM; kk += BKQ) {
        // ---- stage A and B tiles (fp32 -> bf16 hi/lo) ----
#pragma unroll
        for (int i = 0; i < 4; i++) {
            int idx = tid + i * 256;            // 0..1023 float4 slots
            int r  = idx >> 3;                  // 0..127
            int c4 = (idx & 7) * 4;             // 0..28

            // A
            {
                int gr = rowBase + r;
                float4 v = make_float4(0.f, 0.f, 0.f, 0.f);
                if (gr < M) v = *reinterpret_cast<const float4*>(A + (size_t)gr * DIM + kk + c4);
                __nv_bfloat162 h01 = __float22bfloat162_rn(make_float2(v.x, v.y));
                __nv_bfloat162 h23 = __float22bfloat162_rn(make_float2(v.z, v.w));
                __nv_bfloat162 l01 = __float22bfloat162_rn(make_float2(
                    v.x - __bfloat162float(h01.x), v.y - __bfloat162float(h01.y)));
                __nv_bfloat162 l23 = __float22bfloat162_rn(make_float2(
                    v.z - __bfloat162float(h23.x), v.w - __bfloat162float(h23.y)));
                *reinterpret_cast<__nv_bfloat162*>(&Ash[0][r][c4])     = h01;
                *reinterpret_cast<__nv_bfloat162*>(&Ash[0][r][c4 + 2]) = h23;
                *reinterpret_cast<__nv_bfloat162*>(&Ash[1][r][c4])     = l01;
                *reinterpret_cast<__nv_bfloat162*>(&Ash[1][r][c4 + 2]) = l23;
            }
            // B
            {
                int gc = colBase + r;
                float4 v = make_float4(0.f, 0.f, 0.f, 0.f);
                if (gc < Ncols) v = *reinterpret_cast<const float4*>(B + (size_t)gc * DIM + kk + c4);
                __nv_bfloat162 h01 = __float22bfloat162_rn(make_float2(v.x, v.y));
                __nv_bfloat162 h23 = __float22bfloat162_rn(make_float2(v.z, v.w));
                __nv_bfloat162 l01 = __float22bfloat162_rn(make_float2(
                    v.x - __bfloat162float(h01.x), v.y - __bfloat162float(h01.y)));
                __nv_bfloat162 l23 = __float22bfloat162_rn(make_float2(
                    v.z - __bfloat162float(h23.x), v.w - __bfloat162float(h23.y)));
                *reinterpret_cast<__nv_bfloat162*>(&Bsh[0][r][c4])     = h01;
                *reinterpret_cast<__nv_bfloat162*>(&Bsh[0][r][c4 + 2]) = h23;
                *reinterpret_cast<__nv_bfloat162*>(&Bsh[1][r][c4])     = l01;
                *reinterpret_cast<__nv_bfloat162*>(&Bsh[1][r][c4 + 2]) = l23;
            }
        }
        __syncthreads();

        // ---- compute: 2 k-steps of 16 per BK=32 ----
#pragma unroll
        for (int ks = 0; ks < 2; ks++) {
            int k0 = ks * 16;
            unsigned afr[2][4][4];
            unsigned bfr[2][4][2];
#pragma unroll
            for (int hl = 0; hl < 2; hl++) {
#pragma unroll
                for (int i = 0; i < 4; i++) {
                    int r0 = warpRow + i * 16 + rr;
                    afr[hl][i][0] = *reinterpret_cast<const unsigned*>(&Ash[hl][r0][k0 + cc]);
                    afr[hl][i][1] = *reinterpret_cast<const unsigned*>(&Ash[hl][r0 + 8][k0 + cc]);
                    afr[hl][i][2] = *reinterpret_cast<const unsigned*>(&Ash[hl][r0][k0 + cc + 8]);
                    afr[hl][i][3] = *reinterpret_cast<const unsigned*>(&Ash[hl][r0 + 8][k0 + cc + 8]);
                }
#pragma unroll
                for (int j = 0; j < 4; j++) {
                    int n0 = warpCol + j * 8 + rr;
                    bfr[hl][j][0] = *reinterpret_cast<const unsigned*>(&Bsh[hl][n0][k0 + cc]);
                    bfr[hl][j][1] = *reinterpret_cast<const unsigned*>(&Bsh[hl][n0][k0 + cc + 8]);
                }
            }
#pragma unroll
            for (int i = 0; i < 4; i++)
#pragma unroll
                for (int j = 0; j < 4; j++) {
                    mma16816(acc[i][j], afr[0][i], bfr[0][j]);   // hi*hi
                    mma16816(acc[i][j], afr[0][i], bfr[1][j]);   // hi*lo
                    mma16816(acc[i][j], afr[1][i], bfr[0][j]);   // lo*hi
                }
        }
        __syncthreads();
    }

    // ---- epilogue ----
#pragma unroll
    for (int i = 0; i < 4; i++) {
        int gr0 = rowBase + warpRow + i * 16 + rr;
#pragma unroll
        for (int j = 0; j < 4; j++) {
            int gc = colBase + warpCol + j * 8 + cc;
            float b0 = bp ? bp[gc] : 0.f;
            float b1 = bp ? bp[gc + 1] : 0.f;
            if (gr0 < M) {
                C[(size_t)gr0 * Ncols + gc]     = acc[i][j][0] + b0;
                C[(size_t)gr0 * Ncols + gc + 1] = acc[i][j][1] + b1;
            }
            if (gr0 + 8 < M) {
                C[(size_t)(gr0 + 8) * Ncols + gc]     = acc[i][j][2] + b0;
                C[(size_t)(gr0 + 8) * Ncols + gc + 1] = acc[i][j][3] + b1;
            }
        }
    }
}

// ---------------- CSR construction ----------------
__global__ void zero_int_kernel(int* p, int n) {
    int i = blockIdx.x * blockDim.x + threadIdx.x;
    if (i < n) p[i] = 0;
}

__global__ void hist_kernel(const int* __restrict__ dst, int* deg, int E) {
    int i = blockIdx.x * blockDim.x + threadIdx.x;
    if (i < E) atomicAdd(&deg[dst[i]], 1);
}

__global__ void scan_kernel(const int* __restrict__ deg, int* off, int* cur, int n) {
    __shared__ int tmp[1024];
    __shared__ int carry_s;
    int t = threadIdx.x;
    if (t == 0) { off[0] = 0; cur[0] = 0; carry_s = 0; }
    __syncthreads();
    for (int base = 0; base < n; base += 1024) {
        int v = (base + t < n) ? deg[base + t] : 0;
        tmp[t] = v;
        __syncthreads();
        for (int s = 1; s < 1024; s <<= 1) {
            int x = (t >= s) ? tmp[t - s] : 0;
            __syncthreads();
            tmp[t] += x;
            __syncthreads();
        }
        int incl = tmp[t] + carry_s;
        if (base + t < n) { off[base + t + 1] = incl; cur[base + t + 1] = incl; }
        __syncthreads();
        if (t == 1023) carry_s = incl;
        __syncthreads();
    }
}

__global__ void scatter_kernel(const int* __restrict__ src, const int* __restrict__ dst,
                               const int* __restrict__ et, int* cur,
                               int* cgidx, int* csrc, int E, int n) {
    int i = blockIdx.x * blockDim.x + threadIdx.x;
    if (i >= E) return;
    int d = dst[i];
    int p = atomicAdd(&cur[d], 1);
    int s = src[i];
    cgidx[p] = et[i] * n + s;
    csrc[p]  = s;
}

// ---------------- GGC: message aggregation (segment_sum over dst) ----------------
__global__ void agg_kernel(const int* __restrict__ off, const int* __restrict__ cgidx,
                           const float* __restrict__ t, float* __restrict__ a) {
    int n = blockIdx.x, tid = threadIdx.x;  // 128 threads = features
    int s = off[n], e = off[n + 1];
    float acc = 0.f;
    for (int i = s; i < e; i++) {
        int g = __ldg(&cgidx[i]);
        acc += __ldg(&t[(size_t)g * DIM + tid]);
    }
    a[(size_t)n * DIM + tid] = acc;
}

// ---------------- GRU elementwise ----------------
__global__ void gru_kernel(const float* __restrict__ gi, const float* __restrict__ gh,
                           const float* __restrict__ hold, float* __restrict__ hnew, int n) {
    int idx = blockIdx.x * blockDim.x + threadIdx.x;
    if (idx >= n * DIM) return;
    int node = idx >> 7, d = idx & 127;
    const float* gip = gi + (size_t)node * 384;
    const float* ghp = gh + (size_t)node * 384;
    float r  = 1.f / (1.f + expf(-(gip[d] + ghp[d])));
    float zq = 1.f / (1.f + expf(-(gip[128 + d] + ghp[128 + d])));
    float nn = tanhf(gip[256 + d] + r * ghp[256 + d]);
    float h0 = hold[idx];
    hnew[idx] = (1.f - zq) * nn + zq * h0;
}

// ---------------- L2 normalize + sigmoid ----------------
__global__ void normsig_kernel(float* __restrict__ h) {
    int n = blockIdx.x, tid = threadIdx.x;  // 128
    __shared__ float red[128];
    float v = h[(size_t)n * DIM + tid];
    red[tid] = v * v;
    __syncthreads();
    for (int s = 64; s; s >>= 1) {
        if (tid < s) red[tid] += red[tid + s];
        __syncthreads();
    }
    float norm = fmaxf(sqrtf(red[0]), 1e-12f);
    float x = v / norm;
    h[(size_t)n * DIM + tid] = 1.f / (1.f + expf(-x));
}

// ---------------- GAT: el/er per node ----------------
__global__ void eler_kernel(const float* __restrict__ z, const float* __restrict__ al,
                            const float* __restrict__ ar, float* __restrict__ el,
                            float* __restrict__ er) {
    int n = blockIdx.x, tid = threadIdx.x;  // 256 = (head, d)
    __shared__ float sl[256], sr[256];
    float zv = z[(size_t)n * 256 + tid];
    sl[tid] = zv * al[tid];
    sr[tid] = zv * ar[tid];
    __syncthreads();
    int lane = tid & 127;
    for (int s = 64; s; s >>= 1) {
        if (lane < s) { sl[tid] += sl[tid + s]; sr[tid] += sr[tid + s]; }
        __syncthreads();
    }
    if (lane == 0) {
        int h = tid >> 7;
        el[n * 2 + h] = sl[tid];
        er[n * 2 + h] = sr[tid];
    }
}

// ---------------- GAT: edge softmax + weighted aggregation per dst node ----------------
__global__ void gat_kernel(const int* __restrict__ off, const int* __restrict__ csrc,
                           const float* __restrict__ el, const float* __restrict__ er,
                           const float* __restrict__ z, const float* __restrict__ bias,
                           float* __restrict__ outp) {
    int n = blockIdx.x, tid = threadIdx.x;  // 256 = (head, d)
    int h = tid >> 7, lane = tid & 127;
    int s0 = off[n], s1 = off[n + 1];
    float er_nh = er[n * 2 + h];

    __shared__ float red[256];
    __shared__ float mden[4];
    __shared__ float wbuf[2][128];
    __shared__ int   sbuf[128];

    float lmax = -3.0e38f;
    for (int e = s0 + lane; e < s1; e += 128) {
        float x = el[csrc[e] * 2 + h] + er_nh;
        x = x > 0.f ? x : 0.2f * x;
        lmax = fmaxf(lmax, x);
    }
    red[tid] = lmax;
    __syncthreads();
    for (int s = 64; s; s >>= 1) {
        if (lane < s) red[tid] = fmaxf(red[tid], red[tid + s]);
        __syncthreads();
    }
    if (lane == 0) mden[h] = red[tid];
    __syncthreads();
    float m = mden[h];

    float lsum = 0.f;
    for (int e = s0 + lane; e < s1; e += 128) {
        float x = el[csrc[e] * 2 + h] + er_nh;
        x = x > 0.f ? x : 0.2f * x;
        lsum += expf(x - m);
    }
    red[tid] = lsum;
    __syncthreads();
    for (int s = 64; s; s >>= 1) {
        if (lane < s) red[tid] += red[tid + s];
        __syncthreads();
    }
    if (lane == 0) mden[2 + h] = 1.f / red[tid];
    __syncthreads();
    float invden = mden[2 + h];

    float acc = 0.f;
    for (int base = s0; base < s1; base += 128) {
        int cnt = min(128, s1 - base);
        if (lane < cnt) {
            int sn = csrc[base + lane];
            float x = el[sn * 2 + h] + er_nh;
            x = x > 0.f ? x : 0.2f * x;
            wbuf[h][lane] = expf(x - m) * invden;
            if (h == 0) sbuf[lane] = sn;
        }
        __syncthreads();
        for (int i = 0; i < cnt; i++)
            acc = fmaf(wbuf[h][i], z[(size_t)sbuf[i] * 256 + tid], acc);
        __syncthreads();
    }
    float o = acc + bias[tid];
    outp[(size_t)n * 256 + tid] = fmaxf(o, 0.f);
}

// ---------------- graph mean-pool ----------------
__global__ void pool_kernel(const int* __restrict__ gid, const float* __restrict__ hgat,
                            float* __restrict__ hg, int n) {
    int b = blockIdx.x, tid = threadIdx.x;  // 256
    __shared__ int s_lo, s_hi;
    if (tid == 0) {
        int lo = 0, hi = n;
        while (lo < hi) { int mid = (lo + hi) >> 1; if (gid[mid] < b) lo = mid + 1; else hi = mid; }
        s_lo = lo;
        lo = 0; hi = n;
        while (lo < hi) { int mid = (lo + hi) >> 1; if (gid[mid] < b + 1) lo = mid + 1; else hi = mid; }
        s_hi = lo;
    }
    __syncthreads();
    float acc = 0.f;
    for (int node = s_lo; node < s_hi; node++)
        acc += hgat[(size_t)node * 256 + tid];
    float cnt = (float)(s_hi - s_lo);
    hg[b * 256 + tid] = acc / fmaxf(cnt, 1.f);
}

// ---------------- classifier ----------------
__global__ void cls_kernel(const float* __restrict__ hg, const float* __restrict__ Wc,
                           const float* __restrict__ bc, float* __restrict__ outc) {
    int b = blockIdx.x, tid = threadIdx.x;  // 64 = (head, c)
    __shared__ float sh[256];
    for (int i = tid; i < 256; i += 64) sh[i] = hg[b * 256 + i];
    __syncthreads();
    int h = tid >> 5, c = tid & 31;
    float s = bc[c];
    for (int d = 0; d < DIM; d++)
        s = fmaf(sh[h * 128 + d], Wc[c * 128 + d], s);
    outc[b * 64 + tid] = s;
}

// ---------------- pairwise distance + softmax over heads ----------------
__global__ void final_kernel(const float* __restrict__ c1, const float* __restrict__ c2,
                             float* __restrict__ out) {
    int b = threadIdx.x;
    if (b >= NGR) return;
    float dist[2];
    for (int h = 0; h < 2; h++) {
        float ss = 0.f;
        for (int c = 0; c < 32; c++) {
            float diff = c1[b * 64 + h * 32 + c] - c2[b * 64 + h * 32 + c] + 1e-6f;
            ss += diff * diff;
        }
        dist[h] = sqrtf(ss);
    }
    float mx = fmaxf(dist[0], dist[1]);
    float e0 = expf(dist[0] - mx), e1 = expf(dist[1] - mx);
    float inv = 1.f / (e0 + e1);
    out[b * 2 + 0] = e0 * inv;
    out[b * 2 + 1] = e1 * inv;
}

// ---------------- host launcher ----------------
extern "C" void kernel_launch(void* const* d_in, const int* in_sizes, int n_in,
                              void* d_out, int out_size) {
    const float* feat[2] = {(const float*)d_in[0], (const float*)d_in[1]};
    const int* srcs[2] = {(const int*)d_in[2], (const int*)d_in[6]};
    const int* dsts[2] = {(const int*)d_in[3], (const int*)d_in[7]};
    const int* ets[2]  = {(const int*)d_in[4], (const int*)d_in[8]};
    const int* gids[2] = {(const int*)d_in[5], (const int*)d_in[9]};
    const float* W_et   = (const float*)d_in[10];
    const float* b_et   = (const float*)d_in[11];
    const float* W_ih   = (const float*)d_in[12];
    const float* W_hh   = (const float*)d_in[13];
    const float* b_ih   = (const float*)d_in[14];
    const float* b_hh   = (const float*)d_in[15];
    const float* W_fc   = (const float*)d_in[16];
    const float* attn_l = (const float*)d_in[17];
    const float* attn_r = (const float*)d_in[18];
    const float* g_bias = (const float*)d_in[19];
    const float* W_cls  = (const float*)d_in[20];
    const float* b_cls  = (const float*)d_in[21];

    int N = in_sizes[0] / DIM;
    int E = in_sizes[2];

    float *t, *h, *a, *gi, *gh, *z, *gat, *el, *er, *hg, *cls;
    int *deg, *off, *cur, *cgidx, *csrc;
    cudaGetSymbolAddress((void**)&t, g_t);
    cudaGetSymbolAddress((void**)&h, g_h);
    cudaGetSymbolAddress((void**)&a, g_a);
    cudaGetSymbolAddress((void**)&gi, g_gi);
    cudaGetSymbolAddress((void**)&gh, g_gh);
    cudaGetSymbolAddress((void**)&z, g_z);
    cudaGetSymbolAddress((void**)&gat, g_gat);
    cudaGetSymbolAddress((void**)&el, g_el);
    cudaGetSymbolAddress((void**)&er, g_er);
    cudaGetSymbolAddress((void**)&deg, g_deg);
    cudaGetSymbolAddress((void**)&off, g_off);
    cudaGetSymbolAddress((void**)&cur, g_cur);
    cudaGetSymbolAddress((void**)&cgidx, g_cgidx);
    cudaGetSymbolAddress((void**)&csrc, g_csrc);
    cudaGetSymbolAddress((void**)&hg, g_hg);
    cudaGetSymbolAddress((void**)&cls, g_cls);

    int mblocks = (N + 127) / 128;

    for (int g = 0; g < 2; g++) {
        // CSR by dst
        zero_int_kernel<<<(N + 255) / 256, 256>>>(deg, N);
        hist_kernel<<<(E + 255) / 256, 256>>>(dsts[g], deg, E);
        scan_kernel<<<1, 1024>>>(deg, off, cur, N);
        scatter_kernel<<<(E + 255) / 256, 256>>>(srcs[g], dsts[g], ets[g], cur, cgidx, csrc, E, N);

        const float* hcur = feat[g];
        for (int s = 0; s < NSTEPS; s++) {
            // t[k] = hcur @ W_et[k]^T + b_et[k]   (batched over k)
            bgemm_tn<<<dim3(1, mblocks, NET), 256>>>(hcur, W_et, b_et, t,
                                                     N, DIM, DIM * DIM, N * DIM, DIM);
            // a = segment_sum(t[etype,src], dst)
            agg_kernel<<<N, DIM>>>(off, cgidx, t, a);
            // GRU gates
            bgemm_tn<<<dim3(3, mblocks, 1), 256>>>(a, W_ih, b_ih, gi, N, 3 * DIM, 0, 0, 0);
            bgemm_tn<<<dim3(3, mblocks, 1), 256>>>(hcur, W_hh, b_hh, gh, N, 3 * DIM, 0, 0, 0);
            gru_kernel<<<(N * DIM + 255) / 256, 256>>>(gi, gh, hcur, h, N);
            hcur = h;
        }

        normsig_kernel<<<N, DIM>>>(h);

        // GAT
        bgemm_tn<<<dim3(2, mblocks, 1), 256>>>(h, W_fc, nullptr, z, N, 2 * DIM, 0, 0, 0);
        eler_kernel<<<N, 256>>>(z, attn_l, attn_r, el, er);
        gat_kernel<<<N, 256>>>(off, csrc, el, er, z, g_bias, gat);

        // pool + classify
        pool_kernel<<<NGR, 256>>>(gids[g], gat, hg, N);
        cls_kernel<<<NGR, 64>>>(hg, W_cls, b_cls, cls + g * NGR * 64);
    }

    final_kernel<<<1, 64>>>(cls, cls + NGR * 64, (float*)d_out);
}